// round 15
// baseline (speedup 1.0000x reference)
#include <cuda_runtime.h>
#include <cuda_bf16.h>
#include <math.h>
#include <float.h>
#include <stdint.h>

// Problem constants
#define NTOT 65536          // B*H*W
#define CDIM 512            // channels / key dim
#define MDIM 512            // number of memory slots
#define HWDIM 4096          // H*W

// Output packing offsets (flat concat of the returned tuple, fp32)
#define OFF_UQ   0LL
#define OFF_UM   67108864LL           // 16*1024*4096
#define OFF_SQ   67371008LL           // + 512*512
#define OFF_SM   100925440LL          // + 65536*512
#define OFF_SEP  134479872LL          // + 65536*512
#define OFF_COMP 134479873LL

// ---------------- device scratch (no allocations allowed) ----------------
__device__ float          g_E[(size_t)NTOT * MDIM];      // E = exp(score)
__device__ __nv_bfloat16  g_Ah[(size_t)NTOT * CDIM];     // qr hi split
__device__ __nv_bfloat16  g_Al[(size_t)NTOT * CDIM];     // qr lo split
__device__ __nv_bfloat16  g_Sh[(size_t)NTOT * CDIM];     // s_memory hi split
__device__ __nv_bfloat16  g_Sl[(size_t)NTOT * CDIM];     // s_memory lo split
__device__ __nv_bfloat16  g_Bh[(size_t)MDIM * CDIM];     // keys hi
__device__ __nv_bfloat16  g_Bl[(size_t)MDIM * CDIM];     // keys lo
__device__ __nv_bfloat16  g_BTh[(size_t)CDIM * MDIM];    // keysT hi
__device__ __nv_bfloat16  g_BTl[(size_t)CDIM * MDIM];    // keysT lo
__device__ float  g_cmax[MDIM];                   // column max of E
__device__ float  g_csum[MDIM];                   // column sum of E
__device__ float  g_w[NTOT];
__device__ int    g_gi[NTOT];
__device__ int    g_count[MDIM];
__device__ int    g_offset[MDIM + 1];
__device__ int    g_cursor[MDIM];
__device__ int    g_list[NTOT];
__device__ double g_comp, g_sep;

// ---------------- helpers ----------------
__device__ __forceinline__ void atomicMaxF(float* addr, float val) {
    int* ia = (int*)addr;
    int old = *ia;
    while (__int_as_float(old) < val) {
        int assumed = old;
        old = atomicCAS(ia, assumed, __float_as_int(val));
        if (old == assumed) break;
    }
}
__device__ __forceinline__ void bf16split(float v, __nv_bfloat16& h, __nv_bfloat16& l) {
    h = __float2bfloat16(v);
    l = __float2bfloat16(v - __bfloat162float(h));
}
__device__ __forceinline__ uint32_t packbf(__nv_bfloat16 a, __nv_bfloat16 b) {
    __nv_bfloat162 p; p.x = a; p.y = b;
    return *(uint32_t*)&p;
}

// ======================= bf16 3x-split warp-MMA GEMM =======================
// CTA tile 64x128 (8 warps, warp tile 32x32), K-chunk 32, double-buffered
// smem (2 x 24KB), cp.async, 3 CTAs/SM.

__device__ __forceinline__ void ldm4(uint32_t* r, uint32_t a) {
    asm volatile("ldmatrix.sync.aligned.m8n8.x4.shared.b16 {%0,%1,%2,%3}, [%4];"
        : "=r"(r[0]), "=r"(r[1]), "=r"(r[2]), "=r"(r[3]) : "r"(a));
}
__device__ __forceinline__ void mma16816(float* d, const uint32_t* a, uint32_t b0, uint32_t b1) {
    asm volatile("mma.sync.aligned.m16n8k16.row.col.f32.bf16.bf16.f32 "
        "{%0,%1,%2,%3}, {%4,%5,%6,%7}, {%8,%9}, {%0,%1,%2,%3};"
        : "+f"(d[0]), "+f"(d[1]), "+f"(d[2]), "+f"(d[3])
        : "r"(a[0]), "r"(a[1]), "r"(a[2]), "r"(a[3]), "r"(b0), "r"(b1));
}
__device__ __forceinline__ void cpa16(uint32_t dst, const void* src) {
    asm volatile("cp.async.cg.shared.global [%0], [%1], 16;" :: "r"(dst), "l"(src));
}

__device__ __forceinline__ void stage_issue(const __nv_bfloat16* pAh, const __nv_bfloat16* pAl,
                                            const __nv_bfloat16* pBh, const __nv_bfloat16* pBl,
                                            uint32_t stb, uint32_t d0, int koff) {
    cpa16(stb + d0,                  pAh + koff);
    cpa16(stb + 4096u + d0,          pAl + koff);
    cpa16(stb + 8192u + d0,          pBh + koff);
    cpa16(stb + 8192u + d0 + 4096u,  pBh + koff + 32768);
    cpa16(stb + 16384u + d0,         pBl + koff);
    cpa16(stb + 16384u + d0 + 4096u, pBl + koff + 32768);
}

// GEMM body. EPI=0: write E=exp(score)+col stats. EPI=1: rinv-free transposed write.
template <int EPI>
__device__ __forceinline__ void gemm_body(const __nv_bfloat16* __restrict__ Ah,
                                          const __nv_bfloat16* __restrict__ Al,
                                          const __nv_bfloat16* __restrict__ Bh,
                                          const __nv_bfloat16* __restrict__ Bl,
                                          float* __restrict__ Cout,
                                          int bx, int by, char* sm) {
    const int tid = threadIdx.x, lane = tid & 31, wid = tid >> 5;
    const size_t row0 = (size_t)by * 64;
    const int col0 = bx * 128;
    const int warp_i = (wid & 1) * 32;
    const int warp_j = (wid >> 1) * 32;

    float acc[2][4][4];
    #pragma unroll
    for (int a = 0; a < 2; a++)
        #pragma unroll
        for (int b = 0; b < 4; b++)
            #pragma unroll
            for (int c = 0; c < 4; c++) acc[a][b][c] = 0.0f;

    const int lrow = (lane & 7) + ((lane >> 3) & 1) * 8;
    const int lsel = lane >> 4;
    const int arow = warp_i + lrow;
    const int asw  = (arow >> 1) & 3;
    const int brow = warp_j + lrow;
    const int bsw  = (brow >> 1) & 3;
    const uint32_t smb = (uint32_t)__cvta_generic_to_shared(sm);

    const int r0 = tid >> 2, cc4 = tid & 3;
    const uint32_t d0 = (uint32_t)(r0 * 64 + ((cc4 ^ ((r0 >> 1) & 3)) << 4));
    const __nv_bfloat16* pAh = Ah + (row0 + r0) * 512 + cc4 * 8;
    const __nv_bfloat16* pAl = Al + (row0 + r0) * 512 + cc4 * 8;
    const __nv_bfloat16* pBh = Bh + (size_t)(col0 + r0) * 512 + cc4 * 8;
    const __nv_bfloat16* pBl = Bl + (size_t)(col0 + r0) * 512 + cc4 * 8;

    stage_issue(pAh, pAl, pBh, pBl, smb, d0, 0);
    asm volatile("cp.async.commit_group;");

    #pragma unroll 2
    for (int ch = 0; ch < 16; ch++) {
        uint32_t stb = smb + (uint32_t)((ch & 1) ? 24576 : 0);
        if (ch < 15) {
            stage_issue(pAh, pAl, pBh, pBl, smb + (uint32_t)((ch & 1) ? 0 : 24576),
                        d0, (ch + 1) * 32);
            asm volatile("cp.async.commit_group;");
            asm volatile("cp.async.wait_group 1;");
        } else {
            asm volatile("cp.async.wait_group 0;");
        }
        __syncthreads();
        #pragma unroll
        for (int ks = 0; ks < 2; ks++) {
            int cidx = ks * 2 + lsel;
            uint32_t ah[2][4], al[2][4], bh[2][4], bl[2][4];
            #pragma unroll
            for (int fi = 0; fi < 2; fi++) {
                uint32_t ad = stb + (uint32_t)((arow + fi * 16) * 64 + ((cidx ^ asw) << 4));
                ldm4(ah[fi], ad);
                ldm4(al[fi], ad + 4096u);
            }
            #pragma unroll
            for (int g = 0; g < 2; g++) {
                uint32_t bd = stb + 8192u + (uint32_t)((brow + g * 16) * 64 + ((cidx ^ bsw) << 4));
                ldm4(bh[g], bd);
                ldm4(bl[g], bd + 8192u);
            }
            #pragma unroll
            for (int fi = 0; fi < 2; fi++)
                #pragma unroll
                for (int g = 0; g < 2; g++) {
                    mma16816(acc[fi][2*g],   ah[fi], bh[g][0], bh[g][2]);
                    mma16816(acc[fi][2*g+1], ah[fi], bh[g][1], bh[g][3]);
                }
            #pragma unroll
            for (int fi = 0; fi < 2; fi++)
                #pragma unroll
                for (int g = 0; g < 2; g++) {
                    mma16816(acc[fi][2*g],   al[fi], bh[g][0], bh[g][2]);
                    mma16816(acc[fi][2*g+1], al[fi], bh[g][1], bh[g][3]);
                }
            #pragma unroll
            for (int fi = 0; fi < 2; fi++)
                #pragma unroll
                for (int g = 0; g < 2; g++) {
                    mma16816(acc[fi][2*g],   ah[fi], bl[g][0], bl[g][2]);
                    mma16816(acc[fi][2*g+1], ah[fi], bl[g][1], bl[g][3]);
                }
        }
        __syncthreads();
    }

    if (EPI == 0) {
        float e[2][4][4];
        #pragma unroll
        for (int fi = 0; fi < 2; fi++)
            #pragma unroll
            for (int fj = 0; fj < 4; fj++)
                #pragma unroll
                for (int p = 0; p < 4; p++)
                    e[fi][fj][p] = __expf(acc[fi][fj][p]);
        #pragma unroll
        for (int fi = 0; fi < 2; fi++) {
            size_t r = row0 + warp_i + fi * 16 + (lane >> 2);
            #pragma unroll
            for (int fj = 0; fj < 4; fj++) {
                int cw = col0 + warp_j + fj * 8 + (lane & 3) * 2;
                *(float2*)&Cout[r * 512 + cw]       = make_float2(e[fi][fj][0], e[fi][fj][1]);
                *(float2*)&Cout[(r + 8) * 512 + cw] = make_float2(e[fi][fj][2], e[fi][fj][3]);
            }
        }
        float* smax = (float*)sm;
        float* ssum = smax + 128;
        float lmax[4][2], lsum[4][2];
        #pragma unroll
        for (int fj = 0; fj < 4; fj++)
            #pragma unroll
            for (int p = 0; p < 2; p++) {
                float a0 = e[0][fj][p], a1 = e[0][fj][2 + p];
                float a2 = e[1][fj][p], a3 = e[1][fj][2 + p];
                lmax[fj][p] = fmaxf(fmaxf(a0, a1), fmaxf(a2, a3));
                lsum[fj][p] = a0 + a1 + a2 + a3;
            }
        #pragma unroll
        for (int off = 4; off < 32; off <<= 1)
            #pragma unroll
            for (int fj = 0; fj < 4; fj++)
                #pragma unroll
                for (int p = 0; p < 2; p++) {
                    lmax[fj][p] = fmaxf(lmax[fj][p], __shfl_xor_sync(0xffffffffu, lmax[fj][p], off));
                    lsum[fj][p] += __shfl_xor_sync(0xffffffffu, lsum[fj][p], off);
                }
        #pragma unroll
        for (int kk = 0; kk < 2; kk++) {
            if ((wid & 1) == kk && lane < 4) {
                #pragma unroll
                for (int fj = 0; fj < 4; fj++)
                    #pragma unroll
                    for (int p = 0; p < 2; p++) {
                        int c = warp_j + fj * 8 + lane * 2 + p;
                        if (kk == 0) { smax[c] = lmax[fj][p]; ssum[c] = lsum[fj][p]; }
                        else { smax[c] = fmaxf(smax[c], lmax[fj][p]); ssum[c] += lsum[fj][p]; }
                    }
            }
            __syncthreads();
        }
        if (tid < 128) {
            atomicMaxF(&g_cmax[col0 + tid], smax[tid]);
            atomicAdd(&g_csum[col0 + tid], ssum[tid]);
        }
    } else {
        float* tile = (float*)sm;
        size_t b = row0 >> 12;
        int hw0 = (int)(row0 & 4095);
        float* obase = Cout + b * (1024LL * 4096LL) + (size_t)(512 + col0) * 4096;
        #pragma unroll
        for (int fi = 0; fi < 2; fi++) {
            int rr = warp_i + fi * 16 + (lane >> 2);
            #pragma unroll
            for (int fj = 0; fj < 4; fj++) {
                int cw = warp_j + fj * 8 + (lane & 3) * 2;
                tile[rr * 129 + cw]           = acc[fi][fj][0];
                tile[rr * 129 + cw + 1]       = acc[fi][fj][1];
                tile[(rr + 8) * 129 + cw]     = acc[fi][fj][2];
                tile[(rr + 8) * 129 + cw + 1] = acc[fi][fj][3];
            }
        }
        __syncthreads();
        #pragma unroll
        for (int it = 0; it < 16; it++) {
            int d = wid * 16 + it;
            float v0 = tile[lane * 129 + d];
            float v1 = tile[(lane + 32) * 129 + d];
            obase[(size_t)d * 4096 + hw0 + lane]      = v0;
            obase[(size_t)d * 4096 + hw0 + 32 + lane] = v1;
        }
    }
}

__global__ void __launch_bounds__(256, 3) k_mma0(const __nv_bfloat16* __restrict__ Ah,
                                                 const __nv_bfloat16* __restrict__ Al,
                                                 const __nv_bfloat16* __restrict__ Bh,
                                                 const __nv_bfloat16* __restrict__ Bl,
                                                 float* __restrict__ Cout) {
    extern __shared__ char sm[];
    gemm_body<0>(Ah, Al, Bh, Bl, Cout, blockIdx.x, blockIdx.y, sm);
}

// ---------------- memory update body (256 threads; 2 channels/thread) ----------------
__device__ __forceinline__ void update_body(int m, const float* __restrict__ keys,
                                            float* __restrict__ outUM, char* smraw) {
    int t = threadIdx.x;
    int*   sln = (int*)smraw;
    float* slw = (float*)(smraw + 1024);
    float* red = (float*)(smraw + 2048);      // [8]
    float* prn = (float*)(smraw + 2080);
    int beg = g_offset[m], end = g_offset[m + 1];
    float acc0 = 0.0f, acc1 = 0.0f;
    for (int base = beg; base < end; base += 256) {
        int cnt = min(256, end - base);
        __syncthreads();
        if (t < cnt) { int n = g_list[base + t]; sln[t] = n; slw[t] = g_w[n]; }
        __syncthreads();
        for (int i = 0; i < cnt; i++) {
            size_t idx = (size_t)sln[i] * 512 + t;
            float q0 = __bfloat162float(g_Ah[idx]) + __bfloat162float(g_Al[idx]);
            float q1 = __bfloat162float(g_Ah[idx + 256]) + __bfloat162float(g_Al[idx + 256]);
            acc0 += slw[i] * q0;
            acc1 += slw[i] * q1;
        }
    }
    float um0 = acc0 + keys[(size_t)m * 512 + t];
    float um1 = acc1 + keys[(size_t)m * 512 + t + 256];
    float ss = um0 * um0 + um1 * um1;
    #pragma unroll
    for (int o = 16; o; o >>= 1) ss += __shfl_xor_sync(0xffffffffu, ss, o);
    if ((t & 31) == 0) red[t >> 5] = ss;
    __syncthreads();
    if (t == 0) {
        float x = 0.0f;
        #pragma unroll
        for (int i = 0; i < 8; i++) x += red[i];
        *prn = 1.0f / fmaxf(sqrtf(x), 1e-12f);
    }
    __syncthreads();
    float rn = *prn;
    outUM[(size_t)m * 512 + t]       = um0 * rn;
    outUM[(size_t)m * 512 + t + 256] = um1 * rn;
}

// ---------------- fused tail: update (512 blocks) + finalize (1) + GEMM2 (4096) ----------------
__global__ void __launch_bounds__(256, 3) k_tail(const __nv_bfloat16* __restrict__ Sh,
                                                 const __nv_bfloat16* __restrict__ Sl,
                                                 const __nv_bfloat16* __restrict__ BTh,
                                                 const __nv_bfloat16* __restrict__ BTl,
                                                 const float* __restrict__ keys,
                                                 float* __restrict__ out) {
    extern __shared__ char sm[];
    int bid = blockIdx.x;
    if (bid < 512) {
        update_body(bid, keys, out + OFF_UM, sm);
    } else if (bid == 512) {
        if (threadIdx.x == 0) {
            out[OFF_SEP]  = (float)(g_sep / (double)NTOT);
            out[OFF_COMP] = (float)(g_comp / ((double)NTOT * (double)CDIM));
        }
    } else {
        int g = bid - 513;
        gemm_body<1>(Sh, Sl, BTh, BTl, out, g & 3, g >> 2, sm);
    }
}

// ---------------- fused head: normalize (4096) + prepkeys (256) + init (1) ----------------
__global__ void __launch_bounds__(256) k_head(const float* __restrict__ query,
                                              const float* __restrict__ keys,
                                              float* __restrict__ out) {
    int bid = blockIdx.x;
    int tid = threadIdx.x;
    if (bid < 4096) {
        // ---- normalize ----
        __shared__ float s[CDIM * 17];
        __shared__ float psum[256];
        __shared__ float rn[16];
        int p0 = bid * 16;
        int b = p0 >> 12;
        int hw0 = p0 & 4095;
        const float* qb = query + (size_t)b * CDIM * HWDIM + hw0;
        #pragma unroll
        for (int it = 0; it < 32; it++) {
            int i = it * 256 + tid;
            int c = i >> 4, j = i & 15;
            s[c * 17 + j] = qb[(size_t)c * HWDIM + j];
        }
        __syncthreads();
        {
            int j = tid & 15, g = tid >> 4;
            float acc = 0.0f;
            #pragma unroll
            for (int cc = 0; cc < 32; cc++) {
                float v = s[(g * 32 + cc) * 17 + j];
                acc += v * v;
            }
            psum[tid] = acc;
        }
        __syncthreads();
        if (tid < 16) {
            float tot = 0.0f;
            #pragma unroll
            for (int g = 0; g < 16; g++) tot += psum[g * 16 + tid];
            rn[tid] = 1.0f / fmaxf(sqrtf(tot), 1e-12f);
        }
        __syncthreads();
        #pragma unroll
        for (int it = 0; it < 32; it++) {
            int i = it * 256 + tid;
            int c = i & 511, j = i >> 9;
            float v = s[c * 17 + j] * rn[j];
            size_t idx = (size_t)(p0 + j) * CDIM + c;
            __nv_bfloat16 h, l; bf16split(v, h, l);
            g_Ah[idx] = h;
            g_Al[idx] = l;
        }
        float* ob = out + (size_t)b * (1024LL * 4096LL) + hw0;
        #pragma unroll
        for (int it = 0; it < 32; it++) {
            int i = it * 256 + tid;
            int c = i >> 4, j = i & 15;
            ob[(size_t)c * 4096 + j] = s[c * 17 + j] * rn[j];
        }
    } else if (bid < 4352) {
        // ---- prepkeys ----
        __shared__ float t[32][33];
        int pb = bid - 4096;
        int c0 = (pb & 15) * 32;
        int r0 = (pb >> 4) * 32;
        int tx = tid & 31, ty = tid >> 5;
        for (int r = ty; r < 32; r += 8) {
            float v = keys[(size_t)(r0 + r) * 512 + c0 + tx];
            t[r][tx] = v;
            __nv_bfloat16 h, l; bf16split(v, h, l);
            g_Bh[(size_t)(r0 + r) * 512 + c0 + tx] = h;
            g_Bl[(size_t)(r0 + r) * 512 + c0 + tx] = l;
        }
        __syncthreads();
        for (int r = ty; r < 32; r += 8) {
            float v = t[tx][r];
            __nv_bfloat16 h, l; bf16split(v, h, l);
            g_BTh[(size_t)(c0 + r) * 512 + r0 + tx] = h;
            g_BTl[(size_t)(c0 + r) * 512 + r0 + tx] = l;
        }
    } else {
        // ---- init ----
        if (tid < 256) {
            g_cmax[tid] = 0.0f; g_csum[tid] = 0.0f; g_count[tid] = 0;
            g_cmax[tid + 256] = 0.0f; g_csum[tid + 256] = 0.0f; g_count[tid + 256] = 0;
        }
        if (tid == 0) { g_comp = 0.0; g_sep = 0.0; }
    }
}

// ---------------- per-row pass on E (vectorized) ----------------
__global__ void __launch_bounds__(256) k_row(float* __restrict__ out_sq,
                                             float* __restrict__ out_sm,
                                             const float* __restrict__ keys) {
    __shared__ float cinv[512];
    __shared__ double wcomp[8], wsep[8];
    for (int i = threadIdx.x; i < 512; i += 256)
        cinv[i] = 1.0f / g_csum[i];
    __syncthreads();
    int warp = threadIdx.x >> 5, lane = threadIdx.x & 31;
    size_t n = (size_t)blockIdx.x * 8 + warp;
    const float4* erow4 = (const float4*)(g_E + n * 512);
    float4 ev4[4];
    #pragma unroll
    for (int t = 0; t < 4; t++) ev4[t] = erow4[t * 32 + lane];

    float v1 = -FLT_MAX, v2 = -FLT_MAX; int i1 = 0, i2 = 0;
    #pragma unroll
    for (int t = 0; t < 4; t++) {
        const float* e = (const float*)&ev4[t];
        int cb = (t * 32 + lane) * 4;
        #pragma unroll
        for (int j = 0; j < 4; j++) {
            float v = e[j]; int c = cb + j;
            if (v > v1) { v2 = v1; i2 = i1; v1 = v; i1 = c; }
            else if (v > v2) { v2 = v; i2 = c; }
        }
    }
    #pragma unroll
    for (int off = 16; off; off >>= 1) {
        float ov1 = __shfl_down_sync(0xffffffffu, v1, off);
        int   oi1 = __shfl_down_sync(0xffffffffu, i1, off);
        float ov2 = __shfl_down_sync(0xffffffffu, v2, off);
        int   oi2 = __shfl_down_sync(0xffffffffu, i2, off);
        if (ov1 > v1) { v2 = v1; i2 = i1; v1 = ov1; i1 = oi1; if (ov2 > v2) { v2 = ov2; i2 = oi2; } }
        else if (ov1 > v2) { v2 = ov1; i2 = oi1; }
    }
    v1 = __shfl_sync(0xffffffffu, v1, 0);
    i1 = __shfl_sync(0xffffffffu, i1, 0);
    i2 = __shfl_sync(0xffffffffu, i2, 0);

    float rs = 0.0f;
    #pragma unroll
    for (int t = 0; t < 4; t++) rs += ev4[t].x + ev4[t].y + ev4[t].z + ev4[t].w;
    #pragma unroll
    for (int o = 16; o; o >>= 1) rs += __shfl_xor_sync(0xffffffffu, rs, o);
    float inv_rs = 1.0f / rs;

    float4* smrow4 = (float4*)(out_sm + n * 512);
    float4* sqrow4 = (float4*)(out_sq + n * 512);
    #pragma unroll
    for (int t = 0; t < 4; t++) {
        int f4i = t * 32 + lane;
        int cb = f4i * 4;
        const float* e = (const float*)&ev4[t];
        float4 sv = make_float4(e[0] * inv_rs, e[1] * inv_rs, e[2] * inv_rs, e[3] * inv_rs);
        smrow4[f4i] = sv;
        sqrow4[f4i] = make_float4(e[0] * cinv[cb], e[1] * cinv[cb + 1],
                                  e[2] * cinv[cb + 2], e[3] * cinv[cb + 3]);
        __nv_bfloat16 h0, l0, h1, l1, h2, l2, h3, l3;
        bf16split(sv.x, h0, l0); bf16split(sv.y, h1, l1);
        bf16split(sv.z, h2, l2); bf16split(sv.w, h3, l3);
        *(uint2*)&g_Sh[n * 512 + cb] = make_uint2(packbf(h0, h1), packbf(h2, h3));
        *(uint2*)&g_Sl[n * 512 + cb] = make_uint2(packbf(l0, l1), packbf(l2, l3));
    }
    if (lane == 0) {
        g_gi[n] = i1;
        g_w[n] = v1 / g_cmax[i1];
        atomicAdd(&g_count[i1], 1);
    }

    const uint2* qh2 = (const uint2*)(g_Ah + n * 512);
    const uint2* ql2 = (const uint2*)(g_Al + n * 512);
    const float4* pk4 = (const float4*)(keys + (size_t)i1 * 512);
    const float4* nk4 = (const float4*)(keys + (size_t)i2 * 512);
    float comp = 0.0f, dp = 0.0f, dn = 0.0f;
    #pragma unroll
    for (int t = 0; t < 4; t++) {
        int f4i = t * 32 + lane;
        uint2 qhv = qh2[f4i], qlv = ql2[f4i];
        float4 pv = pk4[f4i], nv = nk4[f4i];
        float q[4], p[4], gg[4];
        __nv_bfloat162 hq0 = *(__nv_bfloat162*)&qhv.x, hq1 = *(__nv_bfloat162*)&qhv.y;
        __nv_bfloat162 lq0 = *(__nv_bfloat162*)&qlv.x, lq1 = *(__nv_bfloat162*)&qlv.y;
        q[0] = __bfloat162float(hq0.x) + __bfloat162float(lq0.x);
        q[1] = __bfloat162float(hq0.y) + __bfloat162float(lq0.y);
        q[2] = __bfloat162float(hq1.x) + __bfloat162float(lq1.x);
        q[3] = __bfloat162float(hq1.y) + __bfloat162float(lq1.y);
        p[0] = pv.x; p[1] = pv.y; p[2] = pv.z; p[3] = pv.w;
        gg[0] = nv.x; gg[1] = nv.y; gg[2] = nv.z; gg[3] = nv.w;
        #pragma unroll
        for (int j = 0; j < 4; j++) {
            float d0 = q[j] - p[j]; comp += d0 * d0;
            float d1 = d0 + 1e-6f; dp += d1 * d1;
            float d2 = (q[j] - gg[j]) + 1e-6f; dn += d2 * d2;
        }
    }
    #pragma unroll
    for (int o = 16; o; o >>= 1) {
        comp += __shfl_xor_sync(0xffffffffu, comp, o);
        dp   += __shfl_xor_sync(0xffffffffu, dp, o);
        dn   += __shfl_xor_sync(0xffffffffu, dn, o);
    }
    if (lane == 0) {
        wcomp[warp] = (double)comp;
        wsep[warp] = (double)fmaxf(0.0f, sqrtf(dp) - sqrtf(dn) + 1.0f);
    }
    __syncthreads();
    if (threadIdx.x == 0) {
        double c = 0.0, s = 0.0;
        for (int wv = 0; wv < 8; wv++) { c += wcomp[wv]; s += wsep[wv]; }
        atomicAdd(&g_comp, c);
        atomicAdd(&g_sep, s);
    }
}

// ---------------- counting sort of rows by gi ----------------
__global__ void __launch_bounds__(512) k_scan() {
    __shared__ int s[512];
    int t = threadIdx.x;
    int v = g_count[t];
    s[t] = v;
    __syncthreads();
    for (int off = 1; off < 512; off <<= 1) {
        int add = (t >= off) ? s[t - off] : 0;
        __syncthreads();
        s[t] += add;
        __syncthreads();
    }
    g_offset[t + 1] = s[t];
    if (t == 0) g_offset[0] = 0;
    g_cursor[t] = s[t] - v;
}

__global__ void k_scatter() {
    for (int n = blockIdx.x * blockDim.x + threadIdx.x; n < NTOT; n += gridDim.x * blockDim.x) {
        int m = g_gi[n];
        int idx = atomicAdd(&g_cursor[m], 1);
        g_list[idx] = n;
    }
}

// ---------------- launch ----------------
extern "C" void kernel_launch(void* const* d_in, const int* in_sizes, int n_in,
                              void* d_out, int out_size) {
    const float* query = (const float*)d_in[0];
    const float* keys  = (const float*)d_in[1];
    float* out = (float*)d_out;

    float* p_E = nullptr;
    __nv_bfloat16 *p_Ah = nullptr, *p_Al = nullptr, *p_Sh = nullptr, *p_Sl = nullptr;
    __nv_bfloat16 *p_Bh = nullptr, *p_Bl = nullptr, *p_BTh = nullptr, *p_BTl = nullptr;
    cudaGetSymbolAddress((void**)&p_E, g_E);
    cudaGetSymbolAddress((void**)&p_Ah, g_Ah);
    cudaGetSymbolAddress((void**)&p_Al, g_Al);
    cudaGetSymbolAddress((void**)&p_Sh, g_Sh);
    cudaGetSymbolAddress((void**)&p_Sl, g_Sl);
    cudaGetSymbolAddress((void**)&p_Bh, g_Bh);
    cudaGetSymbolAddress((void**)&p_Bl, g_Bl);
    cudaGetSymbolAddress((void**)&p_BTh, g_BTh);
    cudaGetSymbolAddress((void**)&p_BTl, g_BTl);

    cudaFuncSetAttribute(k_mma0, cudaFuncAttributeMaxDynamicSharedMemorySize, 49152);
    cudaFuncSetAttribute(k_tail, cudaFuncAttributeMaxDynamicSharedMemorySize, 49152);

    k_head<<<4353, 256>>>(query, keys, out);
    k_mma0<<<dim3(4, NTOT / 64), 256, 49152>>>(p_Ah, p_Al, p_Bh, p_Bl, p_E);
    k_row<<<NTOT / 8, 256>>>(out + OFF_SQ, out + OFF_SM, keys);
    k_scan<<<1, 512>>>();
    k_scatter<<<64, 256>>>();
    k_tail<<<4609, 256, 49152>>>(p_Sh, p_Sl, p_BTh, p_BTl, keys, out);
}

// round 16
// speedup vs baseline: 1.1385x; 1.1385x over previous
#include <cuda_runtime.h>
#include <cuda_fp16.h>
#include <math.h>
#include <float.h>
#include <stdint.h>

// Problem constants
#define NTOT 65536          // B*H*W
#define CDIM 512            // channels / key dim
#define MDIM 512            // number of memory slots
#define HWDIM 4096          // H*W

// Output packing offsets (flat concat of the returned tuple, fp32)
#define OFF_UQ   0LL
#define OFF_UM   67108864LL           // 16*1024*4096
#define OFF_SQ   67371008LL           // + 512*512
#define OFF_SM   100925440LL          // + 65536*512
#define OFF_SEP  134479872LL          // + 65536*512
#define OFF_COMP 134479873LL

// ---------------- device scratch (no allocations allowed) ----------------
__device__ float   g_E[(size_t)NTOT * MDIM];      // E = exp(score)
__device__ __half  g_Ah[(size_t)NTOT * CDIM];     // qr hi split (fp16)
__device__ __half  g_Al[(size_t)NTOT * CDIM];     // qr lo split
__device__ __half  g_Sh[(size_t)NTOT * CDIM];     // s_memory fp16 (single)
__device__ __half  g_Bh[(size_t)MDIM * CDIM];     // keys hi
__device__ __half  g_Bl[(size_t)MDIM * CDIM];     // keys lo
__device__ __half  g_BTh[(size_t)CDIM * MDIM];    // keysT hi
__device__ __half  g_BTl[(size_t)CDIM * MDIM];    // keysT lo
__device__ float  g_cmax[MDIM];                   // column max of E
__device__ float  g_csum[MDIM];                   // column sum of E
__device__ float  g_w[NTOT];
__device__ int    g_gi[NTOT];
__device__ int    g_count[MDIM];
__device__ int    g_offset[MDIM + 1];
__device__ int    g_cursor[MDIM];
__device__ int    g_list[NTOT];
__device__ double g_comp, g_sep;

// ---------------- helpers ----------------
__device__ __forceinline__ void atomicMaxF(float* addr, float val) {
    int* ia = (int*)addr;
    int old = *ia;
    while (__int_as_float(old) < val) {
        int assumed = old;
        old = atomicCAS(ia, assumed, __float_as_int(val));
        if (old == assumed) break;
    }
}
__device__ __forceinline__ void fp16split(float v, __half& h, __half& l) {
    h = __float2half_rn(v);
    l = __float2half_rn(v - __half2float(h));
}
__device__ __forceinline__ uint32_t packh(__half a, __half b) {
    __half2 p; p.x = a; p.y = b;
    return *(uint32_t*)&p;
}

// ======================= fp16 split warp-MMA GEMM =======================
// CTA tile 64x128 (8 warps, warp tile 32x32), K-chunk 32, double-buffered
// smem, cp.async, 3 CTAs/SM.

__device__ __forceinline__ void ldm4(uint32_t* r, uint32_t a) {
    asm volatile("ldmatrix.sync.aligned.m8n8.x4.shared.b16 {%0,%1,%2,%3}, [%4];"
        : "=r"(r[0]), "=r"(r[1]), "=r"(r[2]), "=r"(r[3]) : "r"(a));
}
__device__ __forceinline__ void mma16816(float* d, const uint32_t* a, uint32_t b0, uint32_t b1) {
    asm volatile("mma.sync.aligned.m16n8k16.row.col.f32.f16.f16.f32 "
        "{%0,%1,%2,%3}, {%4,%5,%6,%7}, {%8,%9}, {%0,%1,%2,%3};"
        : "+f"(d[0]), "+f"(d[1]), "+f"(d[2]), "+f"(d[3])
        : "r"(a[0]), "r"(a[1]), "r"(a[2]), "r"(a[3]), "r"(b0), "r"(b1));
}
__device__ __forceinline__ void cpa16(uint32_t dst, const void* src) {
    asm volatile("cp.async.cg.shared.global [%0], [%1], 16;" :: "r"(dst), "l"(src));
}

// ---------------- GEMM1: 3-pass (Ah,Al) x (Bh,Bl), E-epilogue ----------------
// Stage 24KB: Ah 0..4K | Al 4K..8K | Bh 8K..16K | Bl 16K..24K
__device__ __forceinline__ void stage_issue1(const __half* pAh, const __half* pAl,
                                             const __half* pBh, const __half* pBl,
                                             uint32_t stb, uint32_t d0, int koff) {
    cpa16(stb + d0,                  pAh + koff);
    cpa16(stb + 4096u + d0,          pAl + koff);
    cpa16(stb + 8192u + d0,          pBh + koff);
    cpa16(stb + 8192u + d0 + 4096u,  pBh + koff + 32768);
    cpa16(stb + 16384u + d0,         pBl + koff);
    cpa16(stb + 16384u + d0 + 4096u, pBl + koff + 32768);
}

__global__ void __launch_bounds__(256, 3) k_mma0(const __half* __restrict__ Ah,
                                                 const __half* __restrict__ Al,
                                                 const __half* __restrict__ Bh,
                                                 const __half* __restrict__ Bl,
                                                 float* __restrict__ Cout) {
    extern __shared__ char sm[];
    const int tid = threadIdx.x, lane = tid & 31, wid = tid >> 5;
    const size_t row0 = (size_t)blockIdx.y * 64;
    const int col0 = blockIdx.x * 128;
    const int warp_i = (wid & 1) * 32;
    const int warp_j = (wid >> 1) * 32;

    float acc[2][4][4];
    #pragma unroll
    for (int a = 0; a < 2; a++)
        #pragma unroll
        for (int b = 0; b < 4; b++)
            #pragma unroll
            for (int c = 0; c < 4; c++) acc[a][b][c] = 0.0f;

    const int lrow = (lane & 7) + ((lane >> 3) & 1) * 8;
    const int lsel = lane >> 4;
    const int arow = warp_i + lrow;
    const int asw  = (arow >> 1) & 3;
    const int brow = warp_j + lrow;
    const int bsw  = (brow >> 1) & 3;
    const uint32_t smb = (uint32_t)__cvta_generic_to_shared(sm);

    const int r0 = tid >> 2, cc4 = tid & 3;
    const uint32_t d0 = (uint32_t)(r0 * 64 + ((cc4 ^ ((r0 >> 1) & 3)) << 4));
    const __half* pAh = Ah + (row0 + r0) * 512 + cc4 * 8;
    const __half* pAl = Al + (row0 + r0) * 512 + cc4 * 8;
    const __half* pBh = Bh + (size_t)(col0 + r0) * 512 + cc4 * 8;
    const __half* pBl = Bl + (size_t)(col0 + r0) * 512 + cc4 * 8;

    stage_issue1(pAh, pAl, pBh, pBl, smb, d0, 0);
    asm volatile("cp.async.commit_group;");

    #pragma unroll 2
    for (int ch = 0; ch < 16; ch++) {
        uint32_t stb = smb + (uint32_t)((ch & 1) ? 24576 : 0);
        if (ch < 15) {
            stage_issue1(pAh, pAl, pBh, pBl, smb + (uint32_t)((ch & 1) ? 0 : 24576),
                         d0, (ch + 1) * 32);
            asm volatile("cp.async.commit_group;");
            asm volatile("cp.async.wait_group 1;");
        } else {
            asm volatile("cp.async.wait_group 0;");
        }
        __syncthreads();
        #pragma unroll
        for (int ks = 0; ks < 2; ks++) {
            int cidx = ks * 2 + lsel;
            uint32_t ah[2][4], al[2][4], bh[2][4], bl[2][4];
            #pragma unroll
            for (int fi = 0; fi < 2; fi++) {
                uint32_t ad = stb + (uint32_t)((arow + fi * 16) * 64 + ((cidx ^ asw) << 4));
                ldm4(ah[fi], ad);
                ldm4(al[fi], ad + 4096u);
            }
            #pragma unroll
            for (int g = 0; g < 2; g++) {
                uint32_t bd = stb + 8192u + (uint32_t)((brow + g * 16) * 64 + ((cidx ^ bsw) << 4));
                ldm4(bh[g], bd);
                ldm4(bl[g], bd + 8192u);
            }
            #pragma unroll
            for (int fi = 0; fi < 2; fi++)
                #pragma unroll
                for (int g = 0; g < 2; g++) {
                    mma16816(acc[fi][2*g],   ah[fi], bh[g][0], bh[g][2]);
                    mma16816(acc[fi][2*g+1], ah[fi], bh[g][1], bh[g][3]);
                }
            #pragma unroll
            for (int fi = 0; fi < 2; fi++)
                #pragma unroll
                for (int g = 0; g < 2; g++) {
                    mma16816(acc[fi][2*g],   al[fi], bh[g][0], bh[g][2]);
                    mma16816(acc[fi][2*g+1], al[fi], bh[g][1], bh[g][3]);
                }
            #pragma unroll
            for (int fi = 0; fi < 2; fi++)
                #pragma unroll
                for (int g = 0; g < 2; g++) {
                    mma16816(acc[fi][2*g],   ah[fi], bl[g][0], bl[g][2]);
                    mma16816(acc[fi][2*g+1], ah[fi], bl[g][1], bl[g][3]);
                }
        }
        __syncthreads();
    }

    // epilogue: E = exp(score), write + col stats
    float e[2][4][4];
    #pragma unroll
    for (int fi = 0; fi < 2; fi++)
        #pragma unroll
        for (int fj = 0; fj < 4; fj++)
            #pragma unroll
            for (int p = 0; p < 4; p++)
                e[fi][fj][p] = __expf(acc[fi][fj][p]);
    #pragma unroll
    for (int fi = 0; fi < 2; fi++) {
        size_t r = row0 + warp_i + fi * 16 + (lane >> 2);
        #pragma unroll
        for (int fj = 0; fj < 4; fj++) {
            int cw = col0 + warp_j + fj * 8 + (lane & 3) * 2;
            *(float2*)&Cout[r * 512 + cw]       = make_float2(e[fi][fj][0], e[fi][fj][1]);
            *(float2*)&Cout[(r + 8) * 512 + cw] = make_float2(e[fi][fj][2], e[fi][fj][3]);
        }
    }
    float* smax = (float*)sm;
    float* ssum = smax + 128;
    float lmax[4][2], lsum[4][2];
    #pragma unroll
    for (int fj = 0; fj < 4; fj++)
        #pragma unroll
        for (int p = 0; p < 2; p++) {
            float a0 = e[0][fj][p], a1 = e[0][fj][2 + p];
            float a2 = e[1][fj][p], a3 = e[1][fj][2 + p];
            lmax[fj][p] = fmaxf(fmaxf(a0, a1), fmaxf(a2, a3));
            lsum[fj][p] = a0 + a1 + a2 + a3;
        }
    #pragma unroll
    for (int off = 4; off < 32; off <<= 1)
        #pragma unroll
        for (int fj = 0; fj < 4; fj++)
            #pragma unroll
            for (int p = 0; p < 2; p++) {
                lmax[fj][p] = fmaxf(lmax[fj][p], __shfl_xor_sync(0xffffffffu, lmax[fj][p], off));
                lsum[fj][p] += __shfl_xor_sync(0xffffffffu, lsum[fj][p], off);
            }
    #pragma unroll
    for (int kk = 0; kk < 2; kk++) {
        if ((wid & 1) == kk && lane < 4) {
            #pragma unroll
            for (int fj = 0; fj < 4; fj++)
                #pragma unroll
                for (int p = 0; p < 2; p++) {
                    int c = warp_j + fj * 8 + lane * 2 + p;
                    if (kk == 0) { smax[c] = lmax[fj][p]; ssum[c] = lsum[fj][p]; }
                    else { smax[c] = fmaxf(smax[c], lmax[fj][p]); ssum[c] += lsum[fj][p]; }
                }
        }
        __syncthreads();
    }
    if (tid < 128) {
        atomicMaxF(&g_cmax[col0 + tid], smax[tid]);
        atomicAdd(&g_csum[col0 + tid], ssum[tid]);
    }
}

// ---------------- GEMM2: 2-pass Sh x (BTh,BTl), transposed epilogue ----------------
// Stage 20KB: Ah 0..4K | Bh 4K..12K | Bl 12K..20K
__device__ __forceinline__ void stage_issue2(const __half* pA, const __half* pBh,
                                             const __half* pBl,
                                             uint32_t stb, uint32_t d0, int koff) {
    cpa16(stb + d0,                  pA + koff);
    cpa16(stb + 4096u + d0,          pBh + koff);
    cpa16(stb + 4096u + d0 + 4096u,  pBh + koff + 32768);
    cpa16(stb + 12288u + d0,         pBl + koff);
    cpa16(stb + 12288u + d0 + 4096u, pBl + koff + 32768);
}

__device__ __forceinline__ void gemm2_body(const __half* __restrict__ A,
                                           const __half* __restrict__ Bh,
                                           const __half* __restrict__ Bl,
                                           float* __restrict__ Cout,
                                           int bx, int by, char* sm) {
    const int tid = threadIdx.x, lane = tid & 31, wid = tid >> 5;
    const size_t row0 = (size_t)by * 64;
    const int col0 = bx * 128;
    const int warp_i = (wid & 1) * 32;
    const int warp_j = (wid >> 1) * 32;

    float acc[2][4][4];
    #pragma unroll
    for (int a = 0; a < 2; a++)
        #pragma unroll
        for (int b = 0; b < 4; b++)
            #pragma unroll
            for (int c = 0; c < 4; c++) acc[a][b][c] = 0.0f;

    const int lrow = (lane & 7) + ((lane >> 3) & 1) * 8;
    const int lsel = lane >> 4;
    const int arow = warp_i + lrow;
    const int asw  = (arow >> 1) & 3;
    const int brow = warp_j + lrow;
    const int bsw  = (brow >> 1) & 3;
    const uint32_t smb = (uint32_t)__cvta_generic_to_shared(sm);

    const int r0 = tid >> 2, cc4 = tid & 3;
    const uint32_t d0 = (uint32_t)(r0 * 64 + ((cc4 ^ ((r0 >> 1) & 3)) << 4));
    const __half* pA  = A  + (row0 + r0) * 512 + cc4 * 8;
    const __half* pBh = Bh + (size_t)(col0 + r0) * 512 + cc4 * 8;
    const __half* pBl = Bl + (size_t)(col0 + r0) * 512 + cc4 * 8;

    stage_issue2(pA, pBh, pBl, smb, d0, 0);
    asm volatile("cp.async.commit_group;");

    #pragma unroll 2
    for (int ch = 0; ch < 16; ch++) {
        uint32_t stb = smb + (uint32_t)((ch & 1) ? 20480 : 0);
        if (ch < 15) {
            stage_issue2(pA, pBh, pBl, smb + (uint32_t)((ch & 1) ? 0 : 20480),
                         d0, (ch + 1) * 32);
            asm volatile("cp.async.commit_group;");
            asm volatile("cp.async.wait_group 1;");
        } else {
            asm volatile("cp.async.wait_group 0;");
        }
        __syncthreads();
        #pragma unroll
        for (int ks = 0; ks < 2; ks++) {
            int cidx = ks * 2 + lsel;
            uint32_t ah[2][4], bh[2][4], bl[2][4];
            #pragma unroll
            for (int fi = 0; fi < 2; fi++) {
                uint32_t ad = stb + (uint32_t)((arow + fi * 16) * 64 + ((cidx ^ asw) << 4));
                ldm4(ah[fi], ad);
            }
            #pragma unroll
            for (int g = 0; g < 2; g++) {
                uint32_t bd = stb + 4096u + (uint32_t)((brow + g * 16) * 64 + ((cidx ^ bsw) << 4));
                ldm4(bh[g], bd);
                ldm4(bl[g], bd + 8192u);
            }
            #pragma unroll
            for (int fi = 0; fi < 2; fi++)
                #pragma unroll
                for (int g = 0; g < 2; g++) {
                    mma16816(acc[fi][2*g],   ah[fi], bh[g][0], bh[g][2]);
                    mma16816(acc[fi][2*g+1], ah[fi], bh[g][1], bh[g][3]);
                }
            #pragma unroll
            for (int fi = 0; fi < 2; fi++)
                #pragma unroll
                for (int g = 0; g < 2; g++) {
                    mma16816(acc[fi][2*g],   ah[fi], bl[g][0], bl[g][2]);
                    mma16816(acc[fi][2*g+1], ah[fi], bl[g][1], bl[g][3]);
                }
        }
        __syncthreads();
    }

    // transposed write via smem tile 64 x 128 fp32, stride 129
    float* tile = (float*)sm;
    size_t b = row0 >> 12;
    int hw0 = (int)(row0 & 4095);
    float* obase = Cout + b * (1024LL * 4096LL) + (size_t)(512 + col0) * 4096;
    #pragma unroll
    for (int fi = 0; fi < 2; fi++) {
        int rr = warp_i + fi * 16 + (lane >> 2);
        #pragma unroll
        for (int fj = 0; fj < 4; fj++) {
            int cw = warp_j + fj * 8 + (lane & 3) * 2;
            tile[rr * 129 + cw]           = acc[fi][fj][0];
            tile[rr * 129 + cw + 1]       = acc[fi][fj][1];
            tile[(rr + 8) * 129 + cw]     = acc[fi][fj][2];
            tile[(rr + 8) * 129 + cw + 1] = acc[fi][fj][3];
        }
    }
    __syncthreads();
    #pragma unroll
    for (int it = 0; it < 16; it++) {
        int d = wid * 16 + it;
        float v0 = tile[lane * 129 + d];
        float v1 = tile[(lane + 32) * 129 + d];
        obase[(size_t)d * 4096 + hw0 + lane]      = v0;
        obase[(size_t)d * 4096 + hw0 + 32 + lane] = v1;
    }
}

// ---------------- memory update body (256 threads; 2 channels/thread) ----------------
__device__ __forceinline__ void update_body(int m, const float* __restrict__ keys,
                                            float* __restrict__ outUM, char* smraw) {
    int t = threadIdx.x;
    int*   sln = (int*)smraw;
    float* slw = (float*)(smraw + 1024);
    float* red = (float*)(smraw + 2048);
    float* prn = (float*)(smraw + 2080);
    int beg = g_offset[m], end = g_offset[m + 1];
    float acc0 = 0.0f, acc1 = 0.0f;
    for (int base = beg; base < end; base += 256) {
        int cnt = min(256, end - base);
        __syncthreads();
        if (t < cnt) { int n = g_list[base + t]; sln[t] = n; slw[t] = g_w[n]; }
        __syncthreads();
        for (int i = 0; i < cnt; i++) {
            size_t idx = (size_t)sln[i] * 512 + t;
            float q0 = __half2float(g_Ah[idx]) + __half2float(g_Al[idx]);
            float q1 = __half2float(g_Ah[idx + 256]) + __half2float(g_Al[idx + 256]);
            acc0 += slw[i] * q0;
            acc1 += slw[i] * q1;
        }
    }
    float um0 = acc0 + keys[(size_t)m * 512 + t];
    float um1 = acc1 + keys[(size_t)m * 512 + t + 256];
    float ss = um0 * um0 + um1 * um1;
    #pragma unroll
    for (int o = 16; o; o >>= 1) ss += __shfl_xor_sync(0xffffffffu, ss, o);
    if ((t & 31) == 0) red[t >> 5] = ss;
    __syncthreads();
    if (t == 0) {
        float x = 0.0f;
        #pragma unroll
        for (int i = 0; i < 8; i++) x += red[i];
        *prn = 1.0f / fmaxf(sqrtf(x), 1e-12f);
    }
    __syncthreads();
    float rn = *prn;
    outUM[(size_t)m * 512 + t]       = um0 * rn;
    outUM[(size_t)m * 512 + t + 256] = um1 * rn;
}

// ---------------- fused tail: update (512) + finalize (1) + GEMM2 (4096) ----------------
__global__ void __launch_bounds__(256, 3) k_tail(const __half* __restrict__ Sh,
                                                 const __half* __restrict__ BTh,
                                                 const __half* __restrict__ BTl,
                                                 const float* __restrict__ keys,
                                                 float* __restrict__ out) {
    extern __shared__ char sm[];
    int bid = blockIdx.x;
    if (bid < 512) {
        update_body(bid, keys, out + OFF_UM, sm);
    } else if (bid == 512) {
        if (threadIdx.x == 0) {
            out[OFF_SEP]  = (float)(g_sep / (double)NTOT);
            out[OFF_COMP] = (float)(g_comp / ((double)NTOT * (double)CDIM));
        }
    } else {
        int g = bid - 513;
        gemm2_body(Sh, BTh, BTl, out, g & 3, g >> 2, sm);
    }
}

// ---------------- fused head: normalize (4096) + prepkeys (256) + init (1) ----------------
__global__ void __launch_bounds__(256) k_head(const float* __restrict__ query,
                                              const float* __restrict__ keys,
                                              float* __restrict__ out) {
    int bid = blockIdx.x;
    int tid = threadIdx.x;
    if (bid < 4096) {
        __shared__ float s[CDIM * 17];
        __shared__ float psum[256];
        __shared__ float rn[16];
        int p0 = bid * 16;
        int b = p0 >> 12;
        int hw0 = p0 & 4095;
        const float* qb = query + (size_t)b * CDIM * HWDIM + hw0;
        #pragma unroll
        for (int it = 0; it < 32; it++) {
            int i = it * 256 + tid;
            int c = i >> 4, j = i & 15;
            s[c * 17 + j] = qb[(size_t)c * HWDIM + j];
        }
        __syncthreads();
        {
            int j = tid & 15, g = tid >> 4;
            float acc = 0.0f;
            #pragma unroll
            for (int cc = 0; cc < 32; cc++) {
                float v = s[(g * 32 + cc) * 17 + j];
                acc += v * v;
            }
            psum[tid] = acc;
        }
        __syncthreads();
        if (tid < 16) {
            float tot = 0.0f;
            #pragma unroll
            for (int g = 0; g < 16; g++) tot += psum[g * 16 + tid];
            rn[tid] = 1.0f / fmaxf(sqrtf(tot), 1e-12f);
        }
        __syncthreads();
        #pragma unroll
        for (int it = 0; it < 32; it++) {
            int i = it * 256 + tid;
            int c = i & 511, j = i >> 9;
            float v = s[c * 17 + j] * rn[j];
            size_t idx = (size_t)(p0 + j) * CDIM + c;
            __half h, l; fp16split(v, h, l);
            g_Ah[idx] = h;
            g_Al[idx] = l;
        }
        float* ob = out + (size_t)b * (1024LL * 4096LL) + hw0;
        #pragma unroll
        for (int it = 0; it < 32; it++) {
            int i = it * 256 + tid;
            int c = i >> 4, j = i & 15;
            ob[(size_t)c * 4096 + j] = s[c * 17 + j] * rn[j];
        }
    } else if (bid < 4352) {
        __shared__ float t[32][33];
        int pb = bid - 4096;
        int c0 = (pb & 15) * 32;
        int r0 = (pb >> 4) * 32;
        int tx = tid & 31, ty = tid >> 5;
        for (int r = ty; r < 32; r += 8) {
            float v = keys[(size_t)(r0 + r) * 512 + c0 + tx];
            t[r][tx] = v;
            __half h, l; fp16split(v, h, l);
            g_Bh[(size_t)(r0 + r) * 512 + c0 + tx] = h;
            g_Bl[(size_t)(r0 + r) * 512 + c0 + tx] = l;
        }
        __syncthreads();
        for (int r = ty; r < 32; r += 8) {
            float v = t[tx][r];
            __half h, l; fp16split(v, h, l);
            g_BTh[(size_t)(c0 + r) * 512 + r0 + tx] = h;
            g_BTl[(size_t)(c0 + r) * 512 + r0 + tx] = l;
        }
    } else {
        if (tid < 256) {
            g_cmax[tid] = 0.0f; g_csum[tid] = 0.0f; g_count[tid] = 0;
            g_cmax[tid + 256] = 0.0f; g_csum[tid + 256] = 0.0f; g_count[tid + 256] = 0;
        }
        if (tid == 0) { g_comp = 0.0; g_sep = 0.0; }
    }
}

// ---------------- per-row pass on E (vectorized) ----------------
__global__ void __launch_bounds__(256) k_row(float* __restrict__ out_sq,
                                             float* __restrict__ out_sm,
                                             const float* __restrict__ keys) {
    __shared__ float cinv[512];
    __shared__ double wcomp[8], wsep[8];
    for (int i = threadIdx.x; i < 512; i += 256)
        cinv[i] = 1.0f / g_csum[i];
    __syncthreads();
    int warp = threadIdx.x >> 5, lane = threadIdx.x & 31;
    size_t n = (size_t)blockIdx.x * 8 + warp;
    const float4* erow4 = (const float4*)(g_E + n * 512);
    float4 ev4[4];
    #pragma unroll
    for (int t = 0; t < 4; t++) ev4[t] = erow4[t * 32 + lane];

    float v1 = -FLT_MAX, v2 = -FLT_MAX; int i1 = 0, i2 = 0;
    #pragma unroll
    for (int t = 0; t < 4; t++) {
        const float* e = (const float*)&ev4[t];
        int cb = (t * 32 + lane) * 4;
        #pragma unroll
        for (int j = 0; j < 4; j++) {
            float v = e[j]; int c = cb + j;
            if (v > v1) { v2 = v1; i2 = i1; v1 = v; i1 = c; }
            else if (v > v2) { v2 = v; i2 = c; }
        }
    }
    #pragma unroll
    for (int off = 16; off; off >>= 1) {
        float ov1 = __shfl_down_sync(0xffffffffu, v1, off);
        int   oi1 = __shfl_down_sync(0xffffffffu, i1, off);
        float ov2 = __shfl_down_sync(0xffffffffu, v2, off);
        int   oi2 = __shfl_down_sync(0xffffffffu, i2, off);
        if (ov1 > v1) { v2 = v1; i2 = i1; v1 = ov1; i1 = oi1; if (ov2 > v2) { v2 = ov2; i2 = oi2; } }
        else if (ov1 > v2) { v2 = ov1; i2 = oi1; }
    }
    v1 = __shfl_sync(0xffffffffu, v1, 0);
    i1 = __shfl_sync(0xffffffffu, i1, 0);
    i2 = __shfl_sync(0xffffffffu, i2, 0);

    float rs = 0.0f;
    #pragma unroll
    for (int t = 0; t < 4; t++) rs += ev4[t].x + ev4[t].y + ev4[t].z + ev4[t].w;
    #pragma unroll
    for (int o = 16; o; o >>= 1) rs += __shfl_xor_sync(0xffffffffu, rs, o);
    float inv_rs = 1.0f / rs;

    float4* smrow4 = (float4*)(out_sm + n * 512);
    float4* sqrow4 = (float4*)(out_sq + n * 512);
    #pragma unroll
    for (int t = 0; t < 4; t++) {
        int f4i = t * 32 + lane;
        int cb = f4i * 4;
        const float* e = (const float*)&ev4[t];
        float4 sv = make_float4(e[0] * inv_rs, e[1] * inv_rs, e[2] * inv_rs, e[3] * inv_rs);
        smrow4[f4i] = sv;
        sqrow4[f4i] = make_float4(e[0] * cinv[cb], e[1] * cinv[cb + 1],
                                  e[2] * cinv[cb + 2], e[3] * cinv[cb + 3]);
        *(uint2*)&g_Sh[n * 512 + cb] =
            make_uint2(packh(__float2half_rn(sv.x), __float2half_rn(sv.y)),
                       packh(__float2half_rn(sv.z), __float2half_rn(sv.w)));
    }
    if (lane == 0) {
        g_gi[n] = i1;
        g_w[n] = v1 / g_cmax[i1];
        atomicAdd(&g_count[i1], 1);
    }

    const uint2* qh2 = (const uint2*)(g_Ah + n * 512);
    const uint2* ql2 = (const uint2*)(g_Al + n * 512);
    const float4* pk4 = (const float4*)(keys + (size_t)i1 * 512);
    const float4* nk4 = (const float4*)(keys + (size_t)i2 * 512);
    float comp = 0.0f, dp = 0.0f, dn = 0.0f;
    #pragma unroll
    for (int t = 0; t < 4; t++) {
        int f4i = t * 32 + lane;
        uint2 qhv = qh2[f4i], qlv = ql2[f4i];
        float4 pv = pk4[f4i], nv = nk4[f4i];
        float q[4], p[4], gg[4];
        __half2 hq0 = *(__half2*)&qhv.x, hq1 = *(__half2*)&qhv.y;
        __half2 lq0 = *(__half2*)&qlv.x, lq1 = *(__half2*)&qlv.y;
        q[0] = __half2float(hq0.x) + __half2float(lq0.x);
        q[1] = __half2float(hq0.y) + __half2float(lq0.y);
        q[2] = __half2float(hq1.x) + __half2float(lq1.x);
        q[3] = __half2float(hq1.y) + __half2float(lq1.y);
        p[0] = pv.x; p[1] = pv.y; p[2] = pv.z; p[3] = pv.w;
        gg[0] = nv.x; gg[1] = nv.y; gg[2] = nv.z; gg[3] = nv.w;
        #pragma unroll
        for (int j = 0; j < 4; j++) {
            float d0 = q[j] - p[j]; comp += d0 * d0;
            float d1 = d0 + 1e-6f; dp += d1 * d1;
            float d2 = (q[j] - gg[j]) + 1e-6f; dn += d2 * d2;
        }
    }
    #pragma unroll
    for (int o = 16; o; o >>= 1) {
        comp += __shfl_xor_sync(0xffffffffu, comp, o);
        dp   += __shfl_xor_sync(0xffffffffu, dp, o);
        dn   += __shfl_xor_sync(0xffffffffu, dn, o);
    }
    if (lane == 0) {
        wcomp[warp] = (double)comp;
        wsep[warp] = (double)fmaxf(0.0f, sqrtf(dp) - sqrtf(dn) + 1.0f);
    }
    __syncthreads();
    if (threadIdx.x == 0) {
        double c = 0.0, s = 0.0;
        for (int wv = 0; wv < 8; wv++) { c += wcomp[wv]; s += wsep[wv]; }
        atomicAdd(&g_comp, c);
        atomicAdd(&g_sep, s);
    }
}

// ---------------- counting sort of rows by gi ----------------
__global__ void __launch_bounds__(512) k_scan() {
    __shared__ int s[512];
    int t = threadIdx.x;
    int v = g_count[t];
    s[t] = v;
    __syncthreads();
    for (int off = 1; off < 512; off <<= 1) {
        int add = (t >= off) ? s[t - off] : 0;
        __syncthreads();
        s[t] += add;
        __syncthreads();
    }
    g_offset[t + 1] = s[t];
    if (t == 0) g_offset[0] = 0;
    g_cursor[t] = s[t] - v;
}

__global__ void k_scatter() {
    for (int n = blockIdx.x * blockDim.x + threadIdx.x; n < NTOT; n += gridDim.x * blockDim.x) {
        int m = g_gi[n];
        int idx = atomicAdd(&g_cursor[m], 1);
        g_list[idx] = n;
    }
}

// ---------------- launch ----------------
extern "C" void kernel_launch(void* const* d_in, const int* in_sizes, int n_in,
                              void* d_out, int out_size) {
    const float* query = (const float*)d_in[0];
    const float* keys  = (const float*)d_in[1];
    float* out = (float*)d_out;

    float* p_E = nullptr;
    __half *p_Ah = nullptr, *p_Al = nullptr, *p_Sh = nullptr;
    __half *p_Bh = nullptr, *p_Bl = nullptr, *p_BTh = nullptr, *p_BTl = nullptr;
    cudaGetSymbolAddress((void**)&p_E, g_E);
    cudaGetSymbolAddress((void**)&p_Ah, g_Ah);
    cudaGetSymbolAddress((void**)&p_Al, g_Al);
    cudaGetSymbolAddress((void**)&p_Sh, g_Sh);
    cudaGetSymbolAddress((void**)&p_Bh, g_Bh);
    cudaGetSymbolAddress((void**)&p_Bl, g_Bl);
    cudaGetSymbolAddress((void**)&p_BTh, g_BTh);
    cudaGetSymbolAddress((void**)&p_BTl, g_BTl);

    cudaFuncSetAttribute(k_mma0, cudaFuncAttributeMaxDynamicSharedMemorySize, 49152);
    cudaFuncSetAttribute(k_tail, cudaFuncAttributeMaxDynamicSharedMemorySize, 49152);

    k_head<<<4353, 256>>>(query, keys, out);
    k_mma0<<<dim3(4, NTOT / 64), 256, 49152>>>(p_Ah, p_Al, p_Bh, p_Bl, p_E);
    k_row<<<NTOT / 8, 256>>>(out + OFF_SQ, out + OFF_SM, keys);
    k_scan<<<1, 512>>>();
    k_scatter<<<64, 256>>>();
    k_tail<<<4609, 256, 49152>>>(p_Sh, p_BTh, p_BTl, keys, out);
}